// round 1
// baseline (speedup 1.0000x reference)
#include <cuda_runtime.h>
#include <cstdint>
#include <math.h>

// Problem constants
constexpr int Bn    = 4;
constexpr int Sn    = 4096;
constexpr int DIMn  = 1024;
constexpr int SDIMn = 256;
constexpr int Mn    = Bn * Sn;          // 16384 tokens
constexpr int TCH   = 32;               // scan chunk length
constexpr int NCH   = Sn / TCH;         // 128 chunks per sequence

// ---------------- scratch (device globals; no allocations) ----------------
__device__ __align__(16) float g_h    [(size_t)Mn * DIMn];   // LN out, later reused as z
__device__ __align__(16) float g_mixed[(size_t)Mn * DIMn];
__device__ __align__(16) float g_u    [(size_t)Mn * DIMn];
__device__ __align__(16) float g_gate [(size_t)Mn * DIMn];
__device__ __align__(16) float g_xs   [(size_t)Mn * SDIMn];
__device__ __align__(16) float g_dec  [(size_t)Mn * SDIMn];
__device__ __align__(16) float g_sel  [(size_t)Mn * SDIMn];
__device__ __align__(16) float g_st   [(size_t)Mn * SDIMn];
__device__ __align__(16) float g_chA  [Bn * NCH * SDIMn];
__device__ __align__(16) float g_chB  [Bn * NCH * SDIMn];
__device__ __align__(16) float g_chS0 [Bn * NCH * SDIMn];

// ---------------- LayerNorm: one block per token row ----------------
__global__ void ln_kernel(const float* __restrict__ x,
                          const float* __restrict__ gw,
                          const float* __restrict__ bw) {
    const int row = blockIdx.x;
    const int t   = threadIdx.x;           // 256 threads, 4 elems each
    const float* xr = x + (size_t)row * DIMn;

    float4 v = *(const float4*)(xr + t * 4);
    float s  = v.x + v.y + v.z + v.w;
    float s2 = fmaf(v.x, v.x, fmaf(v.y, v.y, fmaf(v.z, v.z, v.w * v.w)));

    // warp reduce
    #pragma unroll
    for (int o = 16; o > 0; o >>= 1) {
        s  += __shfl_xor_sync(0xffffffffu, s,  o);
        s2 += __shfl_xor_sync(0xffffffffu, s2, o);
    }
    __shared__ float ws[8], ws2[8];
    __shared__ float s_mu, s_rs;
    const int warp = t >> 5, lane = t & 31;
    if (lane == 0) { ws[warp] = s; ws2[warp] = s2; }
    __syncthreads();
    if (t == 0) {
        float a = 0.f, b = 0.f;
        #pragma unroll
        for (int i = 0; i < 8; i++) { a += ws[i]; b += ws2[i]; }
        float mu  = a * (1.0f / DIMn);
        float var = b * (1.0f / DIMn) - mu * mu;
        s_mu = mu;
        s_rs = rsqrtf(var + 1e-5f);
    }
    __syncthreads();
    const float mu = s_mu, rs = s_rs;

    float4 g4 = *(const float4*)(gw + t * 4);
    float4 b4 = *(const float4*)(bw + t * 4);
    float4 o;
    o.x = (v.x - mu) * rs * g4.x + b4.x;
    o.y = (v.y - mu) * rs * g4.y + b4.y;
    o.z = (v.z - mu) * rs * g4.z + b4.z;
    o.w = (v.w - mu) * rs * g4.w + b4.w;
    *(float4*)(g_h + (size_t)row * DIMn + t * 4) = o;
}

// ---------------- depthwise conv1d (kernel 3, pad 1) ----------------
__global__ void conv_kernel(const float* __restrict__ mw,
                            const float* __restrict__ mb) {
    const int idx = blockIdx.x * blockDim.x + threadIdx.x;   // float4 index
    constexpr int D4 = DIMn / 4;
    if (idx >= Mn * D4) return;
    const int m = idx / D4;
    const int d = (idx - m * D4) * 4;
    const int s = m % Sn;

    const float4 c = *(const float4*)(g_h + (size_t)m * DIMn + d);
    float4 l = make_float4(0.f, 0.f, 0.f, 0.f);
    float4 r = make_float4(0.f, 0.f, 0.f, 0.f);
    if (s > 0)      l = *(const float4*)(g_h + (size_t)(m - 1) * DIMn + d);
    if (s < Sn - 1) r = *(const float4*)(g_h + (size_t)(m + 1) * DIMn + d);

    const float* lc = (const float*)&l;
    const float* cc = (const float*)&c;
    const float* rc = (const float*)&r;
    float4 out;
    float* oc = (float*)&out;
    #pragma unroll
    for (int j = 0; j < 4; j++) {
        const float w0 = __ldg(mw + (d + j) * 3 + 0);
        const float w1 = __ldg(mw + (d + j) * 3 + 1);
        const float w2 = __ldg(mw + (d + j) * 3 + 2);
        oc[j] = fmaf(w0, lc[j], fmaf(w1, cc[j], fmaf(w2, rc[j], __ldg(mb + d + j))));
    }
    *(float4*)(g_mixed + (size_t)m * DIMn + d) = out;
}

// ---------------- chunked linear-recurrence scan ----------------
__global__ void scan_p1() {
    const int b = blockIdx.y, c = blockIdx.x, n = threadIdx.x;
    const size_t base = ((size_t)(b * Sn + c * TCH)) * SDIMn + n;
    float A = 1.f, st = 0.f;
    #pragma unroll
    for (int t = 0; t < TCH; t++) {
        const float d  = g_dec[base + (size_t)t * SDIMn];
        const float xv = g_xs [base + (size_t)t * SDIMn];
        A *= d;
        st = fmaf(d, st, (1.f - d) * xv);
    }
    const int o = (b * NCH + c) * SDIMn + n;
    g_chA[o] = A;
    g_chB[o] = st;
}

__global__ void scan_p2() {
    const int b = blockIdx.x, n = threadIdx.x;
    float s = 0.f;
    #pragma unroll 4
    for (int c = 0; c < NCH; c++) {
        const int o = (b * NCH + c) * SDIMn + n;
        g_chS0[o] = s;
        s = fmaf(g_chA[o], s, g_chB[o]);
    }
}

__global__ void scan_p3() {
    const int b = blockIdx.y, c = blockIdx.x, n = threadIdx.x;
    const size_t base = ((size_t)(b * Sn + c * TCH)) * SDIMn + n;
    float st = g_chS0[(b * NCH + c) * SDIMn + n];
    #pragma unroll
    for (int t = 0; t < TCH; t++) {
        const float d  = g_dec[base + (size_t)t * SDIMn];
        const float xv = g_xs [base + (size_t)t * SDIMn];
        st = fmaf(d, st, (1.f - d) * xv);
        g_st[base + (size_t)t * SDIMn] = st;
    }
}

// ---------------- tiled SGEMM with fused prologue/epilogue ----------------
// C[M,N] = epi( act( A[M,K] @ Bw[K,N] + bias[N] ) )
// PRODA: A element = A[m,k] * A2[m,k]
// EPI 0: act(acc + bias)
// EPI 1: gate:  e1=g, e2=u :  g*(acc+bias) + (1-g)*u
// EPI 2: resid: e1=x      :  acc + bias + x
template <int ACT>
__device__ __forceinline__ float act_apply(float v) {
    if (ACT == 1) return tanhf(v);
    if (ACT == 2) return 1.0f / (1.0f + expf(-v));
    return v;
}

template <int ACT, int EPI, bool PRODA>
__global__ void __launch_bounds__(256)
sgemm(const float* __restrict__ A,  const float* __restrict__ A2,
      const float* __restrict__ Bw, const float* __restrict__ bias,
      float* __restrict__ C,
      const float* __restrict__ e1, const float* __restrict__ e2,
      int N, int K) {
    __shared__ float As[8][128];
    __shared__ float Bs[8][128];

    const int tid = threadIdx.x;
    const int bm = blockIdx.y * 128;
    const int bn = blockIdx.x * 128;

    const int arow = tid >> 1;          // 0..127
    const int acol = (tid & 1) * 4;     // 0 or 4
    const int brow = tid >> 5;          // 0..7
    const int bcol = (tid & 31) * 4;    // 0..124
    const int tx = tid & 15, ty = tid >> 4;

    float acc[8][8];
    #pragma unroll
    for (int i = 0; i < 8; i++)
        #pragma unroll
        for (int j = 0; j < 8; j++) acc[i][j] = 0.f;

    const size_t a_off = (size_t)(bm + arow) * K;

    for (int k0 = 0; k0 < K; k0 += 8) {
        float4 a = *(const float4*)(A + a_off + k0 + acol);
        if (PRODA) {
            float4 a2 = *(const float4*)(A2 + a_off + k0 + acol);
            a.x *= a2.x; a.y *= a2.y; a.z *= a2.z; a.w *= a2.w;
        }
        As[acol + 0][arow] = a.x;
        As[acol + 1][arow] = a.y;
        As[acol + 2][arow] = a.z;
        As[acol + 3][arow] = a.w;
        *(float4*)&Bs[brow][bcol] =
            *(const float4*)(Bw + (size_t)(k0 + brow) * N + bn + bcol);
        __syncthreads();

        #pragma unroll
        for (int kk = 0; kk < 8; kk++) {
            float ra[8], rb[8];
            *(float4*)(ra)     = *(float4*)&As[kk][ty * 8];
            *(float4*)(ra + 4) = *(float4*)&As[kk][ty * 8 + 4];
            *(float4*)(rb)     = *(float4*)&Bs[kk][tx * 8];
            *(float4*)(rb + 4) = *(float4*)&Bs[kk][tx * 8 + 4];
            #pragma unroll
            for (int i = 0; i < 8; i++)
                #pragma unroll
                for (int j = 0; j < 8; j++)
                    acc[i][j] = fmaf(ra[i], rb[j], acc[i][j]);
        }
        __syncthreads();
    }

    // epilogue
    #pragma unroll
    for (int i = 0; i < 8; i++) {
        const size_t m = (size_t)(bm + ty * 8 + i);
        #pragma unroll
        for (int jb = 0; jb < 8; jb += 4) {
            const int n = bn + tx * 8 + jb;
            const float4 bs = *(const float4*)(bias + n);
            float v[4] = { acc[i][jb] + bs.x, acc[i][jb + 1] + bs.y,
                           acc[i][jb + 2] + bs.z, acc[i][jb + 3] + bs.w };
            float4 o;
            if (EPI == 0) {
                o.x = act_apply<ACT>(v[0]); o.y = act_apply<ACT>(v[1]);
                o.z = act_apply<ACT>(v[2]); o.w = act_apply<ACT>(v[3]);
            } else if (EPI == 1) {
                const float4 g4 = *(const float4*)(e1 + m * N + n);
                const float4 u4 = *(const float4*)(e2 + m * N + n);
                o.x = g4.x * v[0] + (1.f - g4.x) * u4.x;
                o.y = g4.y * v[1] + (1.f - g4.y) * u4.y;
                o.z = g4.z * v[2] + (1.f - g4.z) * u4.z;
                o.w = g4.w * v[3] + (1.f - g4.w) * u4.w;
            } else { // EPI == 2
                const float4 x4 = *(const float4*)(e1 + m * N + n);
                o.x = v[0] + x4.x; o.y = v[1] + x4.y;
                o.z = v[2] + x4.z; o.w = v[3] + x4.w;
            }
            *(float4*)(C + m * N + n) = o;
        }
    }
}

// ---------------- launcher ----------------
extern "C" void kernel_launch(void* const* d_in, const int* in_sizes, int n_in,
                              void* d_out, int out_size) {
    const float* x    = (const float*)d_in[0];
    const float* ln_g = (const float*)d_in[1];
    const float* ln_b = (const float*)d_in[2];
    const float* mixw = (const float*)d_in[3];
    const float* mixb = (const float*)d_in[4];
    const float* Wi   = (const float*)d_in[5];
    const float* bi   = (const float*)d_in[6];
    const float* Wsin = (const float*)d_in[7];
    const float* bsin = (const float*)d_in[8];
    const float* Wd   = (const float*)d_in[9];
    const float* bd   = (const float*)d_in[10];
    const float* Wsel = (const float*)d_in[11];
    const float* bsel = (const float*)d_in[12];
    const float* Wso  = (const float*)d_in[13];
    const float* bso  = (const float*)d_in[14];
    const float* Wg   = (const float*)d_in[15];
    const float* bg   = (const float*)d_in[16];
    const float* Wout = (const float*)d_in[17];
    const float* bout = (const float*)d_in[18];

    float *p_h, *p_mixed, *p_u, *p_gate, *p_xs, *p_dec, *p_sel, *p_st;
    cudaGetSymbolAddress((void**)&p_h,     g_h);
    cudaGetSymbolAddress((void**)&p_mixed, g_mixed);
    cudaGetSymbolAddress((void**)&p_u,     g_u);
    cudaGetSymbolAddress((void**)&p_gate,  g_gate);
    cudaGetSymbolAddress((void**)&p_xs,    g_xs);
    cudaGetSymbolAddress((void**)&p_dec,   g_dec);
    cudaGetSymbolAddress((void**)&p_sel,   g_sel);
    cudaGetSymbolAddress((void**)&p_st,    g_st);

    // 1) LayerNorm
    ln_kernel<<<Mn, 256>>>(x, ln_g, ln_b);

    // 2) depthwise conv
    {
        const int nf4 = Mn * DIMn / 4;
        conv_kernel<<<(nf4 + 255) / 256, 256>>>(mixw, mixb);
    }

    dim3 g256(SDIMn / 128, Mn / 128);
    dim3 g1024(DIMn / 128, Mn / 128);

    // 3) small projections feeding the scan first (keeps them L2-hot)
    sgemm<1, 0, false><<<g256, 256>>>(p_mixed, nullptr, Wsin, bsin, p_xs,
                                      nullptr, nullptr, SDIMn, DIMn);
    sgemm<2, 0, false><<<g256, 256>>>(p_mixed, nullptr, Wd, bd, p_dec,
                                      nullptr, nullptr, SDIMn, DIMn);

    // 4) chunked scan
    scan_p1<<<dim3(NCH, Bn), SDIMn>>>();
    scan_p2<<<Bn, SDIMn>>>();
    scan_p3<<<dim3(NCH, Bn), SDIMn>>>();

    // 5) remaining projections
    sgemm<2, 0, false><<<g256, 256>>>(p_mixed, nullptr, Wsel, bsel, p_sel,
                                      nullptr, nullptr, SDIMn, DIMn);
    sgemm<1, 0, false><<<g1024, 256>>>(p_mixed, nullptr, Wi, bi, p_u,
                                       nullptr, nullptr, DIMn, DIMn);
    sgemm<2, 0, false><<<g1024, 256>>>(p_mixed, nullptr, Wg, bg, p_gate,
                                       nullptr, nullptr, DIMn, DIMn);

    // 6) y = (sel*states)@Wso + bso, fused gate:  z = g*y + (1-g)*u  (z -> g_h)
    sgemm<0, 1, true><<<g1024, 256>>>(p_sel, p_st, Wso, bso, p_h,
                                      p_gate, p_u, DIMn, SDIMn);

    // 7) out = z@Wout + bout + x
    sgemm<0, 2, false><<<g1024, 256>>>(p_h, nullptr, Wout, bout, (float*)d_out,
                                       x, nullptr, DIMn, DIMn);
}

// round 3
// speedup vs baseline: 2.7563x; 2.7563x over previous
#include <cuda_runtime.h>
#include <cstdint>
#include <math.h>

// Problem constants
constexpr int Bn    = 4;
constexpr int Sn    = 4096;
constexpr int DIMn  = 1024;
constexpr int SDIMn = 256;
constexpr int Mn    = Bn * Sn;          // 16384 tokens
constexpr int TCH   = 32;               // scan chunk length
constexpr int NCH   = Sn / TCH;         // 128 chunks per sequence

// ---------------- scratch (device globals; no allocations) ----------------
__device__ __align__(16) float g_h    [(size_t)Mn * DIMn];   // LN out, later z
__device__ __align__(16) float g_mixed[(size_t)Mn * DIMn];
__device__ __align__(16) float g_u    [(size_t)Mn * DIMn];
__device__ __align__(16) float g_gate [(size_t)Mn * DIMn];
__device__ __align__(16) float g_xs   [(size_t)Mn * SDIMn];
__device__ __align__(16) float g_dec  [(size_t)Mn * SDIMn];
__device__ __align__(16) float g_sel  [(size_t)Mn * SDIMn];
__device__ __align__(16) float g_st   [(size_t)Mn * SDIMn];  // round(sel*state)
__device__ __align__(16) float g_chA  [Bn * NCH * SDIMn];
__device__ __align__(16) float g_chB  [Bn * NCH * SDIMn];
__device__ __align__(16) float g_chS0 [Bn * NCH * SDIMn];

// transposed (and tf32-rounded) weights, packed
constexpr size_t SZ_SD = (size_t)SDIMn * DIMn;   // 262144
constexpr size_t SZ_DD = (size_t)DIMn * DIMn;    // 1048576
constexpr size_t OFF_WSIN = 0;
constexpr size_t OFF_WD   = OFF_WSIN + SZ_SD;
constexpr size_t OFF_WSEL = OFF_WD   + SZ_SD;
constexpr size_t OFF_WSO  = OFF_WSEL + SZ_SD;
constexpr size_t OFF_WI   = OFF_WSO  + SZ_SD;
constexpr size_t OFF_WG   = OFF_WI   + SZ_DD;
constexpr size_t OFF_WOUT = OFF_WG   + SZ_DD;
__device__ __align__(16) float g_wT[OFF_WOUT + SZ_DD];

// ---------------- helpers ----------------
__device__ __forceinline__ float tf32rna(float v) {
    uint32_t u;
    asm("cvt.rna.tf32.f32 %0, %1;" : "=r"(u) : "f"(v));
    return __uint_as_float(u);
}
__device__ __forceinline__ uint32_t smem_u32(const void* p) {
    uint32_t a;
    asm("{ .reg .u64 t; cvta.to.shared.u64 t, %1; cvt.u32.u64 %0, t; }"
        : "=r"(a) : "l"(p));
    return a;
}
__device__ __forceinline__ void cpa16(uint32_t s, const void* g) {
    asm volatile("cp.async.cg.shared.global [%0], [%1], 16;" :: "r"(s), "l"(g));
}
__device__ __forceinline__ void mma8(float* d, const uint32_t* a, const uint32_t* b) {
    asm volatile(
        "mma.sync.aligned.m16n8k8.row.col.f32.tf32.tf32.f32 "
        "{%0,%1,%2,%3}, {%4,%5,%6,%7}, {%8,%9}, {%0,%1,%2,%3};"
        : "+f"(d[0]), "+f"(d[1]), "+f"(d[2]), "+f"(d[3])
        : "r"(a[0]), "r"(a[1]), "r"(a[2]), "r"(a[3]), "r"(b[0]), "r"(b[1]));
}

// ---------------- LayerNorm ----------------
__global__ void ln_kernel(const float* __restrict__ x,
                          const float* __restrict__ gw,
                          const float* __restrict__ bw) {
    const int row = blockIdx.x;
    const int t   = threadIdx.x;
    const float* xr = x + (size_t)row * DIMn;

    float4 v = *(const float4*)(xr + t * 4);
    float s  = v.x + v.y + v.z + v.w;
    float s2 = fmaf(v.x, v.x, fmaf(v.y, v.y, fmaf(v.z, v.z, v.w * v.w)));
    #pragma unroll
    for (int o = 16; o > 0; o >>= 1) {
        s  += __shfl_xor_sync(0xffffffffu, s,  o);
        s2 += __shfl_xor_sync(0xffffffffu, s2, o);
    }
    __shared__ float ws[8], ws2[8];
    __shared__ float s_mu, s_rs;
    const int warp = t >> 5, lane = t & 31;
    if (lane == 0) { ws[warp] = s; ws2[warp] = s2; }
    __syncthreads();
    if (t == 0) {
        float a = 0.f, b = 0.f;
        #pragma unroll
        for (int i = 0; i < 8; i++) { a += ws[i]; b += ws2[i]; }
        float mu  = a * (1.0f / DIMn);
        float var = b * (1.0f / DIMn) - mu * mu;
        s_mu = mu; s_rs = rsqrtf(var + 1e-5f);
    }
    __syncthreads();
    const float mu = s_mu, rs = s_rs;
    float4 g4 = *(const float4*)(gw + t * 4);
    float4 b4 = *(const float4*)(bw + t * 4);
    float4 o;
    o.x = (v.x - mu) * rs * g4.x + b4.x;
    o.y = (v.y - mu) * rs * g4.y + b4.y;
    o.z = (v.z - mu) * rs * g4.z + b4.z;
    o.w = (v.w - mu) * rs * g4.w + b4.w;
    *(float4*)(g_h + (size_t)row * DIMn + t * 4) = o;
}

// ---------------- depthwise conv1d (output tf32-rounded) ----------------
__global__ void conv_kernel(const float* __restrict__ mw,
                            const float* __restrict__ mb) {
    const int idx = blockIdx.x * blockDim.x + threadIdx.x;
    constexpr int D4 = DIMn / 4;
    if (idx >= Mn * D4) return;
    const int m = idx / D4;
    const int d = (idx - m * D4) * 4;
    const int s = m % Sn;

    const float4 c = *(const float4*)(g_h + (size_t)m * DIMn + d);
    float4 l = make_float4(0.f, 0.f, 0.f, 0.f);
    float4 r = make_float4(0.f, 0.f, 0.f, 0.f);
    if (s > 0)      l = *(const float4*)(g_h + (size_t)(m - 1) * DIMn + d);
    if (s < Sn - 1) r = *(const float4*)(g_h + (size_t)(m + 1) * DIMn + d);

    const float* lc = (const float*)&l;
    const float* cc = (const float*)&c;
    const float* rc = (const float*)&r;
    float4 out; float* oc = (float*)&out;
    #pragma unroll
    for (int j = 0; j < 4; j++) {
        const float w0 = __ldg(mw + (d + j) * 3 + 0);
        const float w1 = __ldg(mw + (d + j) * 3 + 1);
        const float w2 = __ldg(mw + (d + j) * 3 + 2);
        oc[j] = tf32rna(fmaf(w0, lc[j], fmaf(w1, cc[j],
                         fmaf(w2, rc[j], __ldg(mb + d + j)))));
    }
    *(float4*)(g_mixed + (size_t)m * DIMn + d) = out;
}

// ---------------- chunked scan ----------------
__global__ void scan_p1() {
    const int b = blockIdx.y, c = blockIdx.x, n = threadIdx.x;
    const size_t base = ((size_t)(b * Sn + c * TCH)) * SDIMn + n;
    float A = 1.f, st = 0.f;
    #pragma unroll
    for (int t = 0; t < TCH; t++) {
        const float d  = g_dec[base + (size_t)t * SDIMn];
        const float xv = g_xs [base + (size_t)t * SDIMn];
        A *= d;
        st = fmaf(d, st, (1.f - d) * xv);
    }
    const int o = (b * NCH + c) * SDIMn + n;
    g_chA[o] = A; g_chB[o] = st;
}
__global__ void scan_p2() {
    const int b = blockIdx.x, n = threadIdx.x;
    float s = 0.f;
    #pragma unroll 4
    for (int c = 0; c < NCH; c++) {
        const int o = (b * NCH + c) * SDIMn + n;
        g_chS0[o] = s;
        s = fmaf(g_chA[o], s, g_chB[o]);
    }
}
// p3 also fuses sel*state product (tf32-rounded) -> A operand of Wso GEMM
__global__ void scan_p3() {
    const int b = blockIdx.y, c = blockIdx.x, n = threadIdx.x;
    const size_t base = ((size_t)(b * Sn + c * TCH)) * SDIMn + n;
    float st = g_chS0[(b * NCH + c) * SDIMn + n];
    #pragma unroll
    for (int t = 0; t < TCH; t++) {
        const float d  = g_dec[base + (size_t)t * SDIMn];
        const float xv = g_xs [base + (size_t)t * SDIMn];
        st = fmaf(d, st, (1.f - d) * xv);
        const float sl = g_sel[base + (size_t)t * SDIMn];
        g_st[base + (size_t)t * SDIMn] = tf32rna(sl * st);
    }
}

// ---------------- weight transpose + tf32 round: Wt[n][k] = rna(W[k][n]) ----
__global__ void transpose_kernel(const float* __restrict__ in,
                                 float* __restrict__ out, int K, int N) {
    __shared__ float tile[32][33];
    const int n0 = blockIdx.x * 32, k0 = blockIdx.y * 32;
    const int tx = threadIdx.x, ty = threadIdx.y;   // 32 x 8
    #pragma unroll
    for (int j = 0; j < 32; j += 8)
        tile[ty + j][tx] = in[(size_t)(k0 + ty + j) * N + n0 + tx];
    __syncthreads();
    #pragma unroll
    for (int j = 0; j < 32; j += 8)
        out[(size_t)(n0 + ty + j) * K + k0 + tx] = tf32rna(tile[tx][ty + j]);
}

// ---------------- tf32 mma.sync GEMM ----------------
// C[M,N] = epi( A[M,K] @ Bt[N,K]^T + bias )
// ACT: 0 none, 1 tanh, 2 sigmoid
// EPI 0: act(v); 1: round(g*v+(1-g)*u) [z]; 2: v + x [residual]
template <int ACT>
__device__ __forceinline__ float act_apply(float v) {
    if (ACT == 1) return tanhf(v);
    if (ACT == 2) return 1.0f / (1.0f + expf(-v));
    return v;
}

template <int ACT, int EPI>
__global__ void __launch_bounds__(256, 2)
mma_gemm(const float* __restrict__ A, const float* __restrict__ Bt,
         const float* __restrict__ bias, float* __restrict__ C,
         const float* __restrict__ e1, const float* __restrict__ e2,
         int N, int K) {
    __shared__ float sm[2][2][128 * 20];   // 40960 B

    const int tid  = threadIdx.x;
    const int wid  = tid >> 5;
    const int lane = tid & 31;
    const int g    = lane >> 2;     // groupID 0..7
    const int tg   = lane & 3;      // thread-in-group 0..3
    const int wm   = wid & 1;       // warp row (64 rows each)
    const int wn   = wid >> 1;      // warp col (32 cols each)
    const int bm   = blockIdx.y * 128;
    const int bn   = blockIdx.x * 128;

    const int srow0 = tid >> 2;             // 0..63
    const int sc4   = (tid & 3) * 4;        // 0,4,8,12
    const uint32_t sAa[2] = { smem_u32(&sm[0][0][0]), smem_u32(&sm[1][0][0]) };
    const uint32_t sBa[2] = { smem_u32(&sm[0][1][0]), smem_u32(&sm[1][1][0]) };

    const int NKS = K >> 4;

    auto stage = [&](int buf, int ks) {
        #pragma unroll
        for (int r = 0; r < 2; r++) {
            const int row = srow0 + 64 * r;
            const uint32_t so = (uint32_t)((row * 20 + sc4) * 4);
            cpa16(sAa[buf] + so, A  + (size_t)(bm + row) * K + ks * 16 + sc4);
            cpa16(sBa[buf] + so, Bt + (size_t)(bn + row) * K + ks * 16 + sc4);
        }
        asm volatile("cp.async.commit_group;" ::: "memory");
    };

    float acc[4][4][4];
    #pragma unroll
    for (int i = 0; i < 4; i++)
        #pragma unroll
        for (int j = 0; j < 4; j++)
            #pragma unroll
            for (int q = 0; q < 4; q++) acc[i][j][q] = 0.f;

    stage(0, 0);
    stage(1, 1);

    for (int ks = 0; ks < NKS; ks++) {
        if (ks + 1 < NKS) asm volatile("cp.async.wait_group 1;" ::: "memory");
        else              asm volatile("cp.async.wait_group 0;" ::: "memory");
        __syncthreads();

        const float* As = &sm[ks & 1][0][0];
        const float* Bs = &sm[ks & 1][1][0];

        #pragma unroll
        for (int kk = 0; kk < 2; kk++) {
            const int k0 = kk * 8;
            uint32_t a[4][4], b[4][2];
            #pragma unroll
            for (int i = 0; i < 4; i++) {
                const float* ap = As + (wm * 64 + i * 16 + g) * 20 + k0 + tg;
                a[i][0] = __float_as_uint(ap[0]);
                a[i][1] = __float_as_uint(ap[8 * 20]);
                a[i][2] = __float_as_uint(ap[4]);
                a[i][3] = __float_as_uint(ap[8 * 20 + 4]);
            }
            #pragma unroll
            for (int j = 0; j < 4; j++) {
                const float* bp = Bs + (wn * 32 + j * 8 + g) * 20 + k0 + tg;
                b[j][0] = __float_as_uint(bp[0]);
                b[j][1] = __float_as_uint(bp[4]);
            }
            #pragma unroll
            for (int i = 0; i < 4; i++)
                #pragma unroll
                for (int j = 0; j < 4; j++)
                    mma8(acc[i][j], a[i], b[j]);
        }
        __syncthreads();
        if (ks + 2 < NKS) stage(ks & 1, ks + 2);
    }

    // ---- epilogue ----
    #pragma unroll
    for (int i = 0; i < 4; i++) {
        const int r0 = bm + wm * 64 + i * 16 + g;
        #pragma unroll
        for (int j = 0; j < 4; j++) {
            const int c0 = bn + wn * 32 + j * 8 + 2 * tg;
            const float2 bs = *(const float2*)(bias + c0);
            #pragma unroll
            for (int h = 0; h < 2; h++) {
                const int row = r0 + 8 * h;
                const float v0 = acc[i][j][2 * h]     + bs.x;
                const float v1 = acc[i][j][2 * h + 1] + bs.y;
                float2 o;
                if (EPI == 0) {
                    o.x = act_apply<ACT>(v0);
                    o.y = act_apply<ACT>(v1);
                } else if (EPI == 1) {
                    const float2 gg = *(const float2*)(e1 + (size_t)row * N + c0);
                    const float2 uu = *(const float2*)(e2 + (size_t)row * N + c0);
                    o.x = tf32rna(gg.x * v0 + (1.f - gg.x) * uu.x);
                    o.y = tf32rna(gg.y * v1 + (1.f - gg.y) * uu.y);
                } else {
                    const float2 xx = *(const float2*)(e1 + (size_t)row * N + c0);
                    o.x = v0 + xx.x;
                    o.y = v1 + xx.y;
                }
                *(float2*)(C + (size_t)row * N + c0) = o;
            }
        }
    }
}

// ---------------- launcher ----------------
extern "C" void kernel_launch(void* const* d_in, const int* in_sizes, int n_in,
                              void* d_out, int out_size) {
    const float* x    = (const float*)d_in[0];
    const float* ln_g = (const float*)d_in[1];
    const float* ln_b = (const float*)d_in[2];
    const float* mixw = (const float*)d_in[3];
    const float* mixb = (const float*)d_in[4];
    const float* Wi   = (const float*)d_in[5];
    const float* bi   = (const float*)d_in[6];
    const float* Wsin = (const float*)d_in[7];
    const float* bsin = (const float*)d_in[8];
    const float* Wd   = (const float*)d_in[9];
    const float* bd   = (const float*)d_in[10];
    const float* Wsel = (const float*)d_in[11];
    const float* bsel = (const float*)d_in[12];
    const float* Wso  = (const float*)d_in[13];
    const float* bso  = (const float*)d_in[14];
    const float* Wg   = (const float*)d_in[15];
    const float* bg   = (const float*)d_in[16];
    const float* Wout = (const float*)d_in[17];
    const float* bout = (const float*)d_in[18];

    float *p_h, *p_mixed, *p_u, *p_gate, *p_xs, *p_dec, *p_sel, *p_st, *p_wT;
    cudaGetSymbolAddress((void**)&p_h,     g_h);
    cudaGetSymbolAddress((void**)&p_mixed, g_mixed);
    cudaGetSymbolAddress((void**)&p_u,     g_u);
    cudaGetSymbolAddress((void**)&p_gate,  g_gate);
    cudaGetSymbolAddress((void**)&p_xs,    g_xs);
    cudaGetSymbolAddress((void**)&p_dec,   g_dec);
    cudaGetSymbolAddress((void**)&p_sel,   g_sel);
    cudaGetSymbolAddress((void**)&p_st,    g_st);
    cudaGetSymbolAddress((void**)&p_wT,    g_wT);

    const dim3 tb(32, 8);
    auto tr = [&](const float* W, size_t off, int K, int N) {
        transpose_kernel<<<dim3(N / 32, K / 32), tb>>>(W, p_wT + off, K, N);
    };

    // 0) all weight transposes up front
    tr(Wsin, OFF_WSIN, DIMn, SDIMn);
    tr(Wd,   OFF_WD,   DIMn, SDIMn);
    tr(Wsel, OFF_WSEL, DIMn, SDIMn);
    tr(Wso,  OFF_WSO,  SDIMn, DIMn);
    tr(Wi,   OFF_WI,   DIMn, DIMn);
    tr(Wg,   OFF_WG,   DIMn, DIMn);
    tr(Wout, OFF_WOUT, DIMn, DIMn);

    // 1) LayerNorm + depthwise conv (conv rounds to tf32)
    ln_kernel<<<Mn, 256>>>(x, ln_g, ln_b);
    {
        const int nf4 = Mn * DIMn / 4;
        conv_kernel<<<(nf4 + 255) / 256, 256>>>(mixw, mixb);
    }

    const dim3 g256(SDIMn / 128, Mn / 128);   // N=256
    const dim3 g1024(DIMn / 128, Mn / 128);   // N=1024

    // 2) projections feeding the scan (+ sel before scan_p3)
    mma_gemm<1, 0><<<g256, 256>>>(p_mixed, p_wT + OFF_WSIN, bsin, p_xs,
                                  nullptr, nullptr, SDIMn, DIMn);
    mma_gemm<2, 0><<<g256, 256>>>(p_mixed, p_wT + OFF_WD, bd, p_dec,
                                  nullptr, nullptr, SDIMn, DIMn);
    mma_gemm<2, 0><<<g256, 256>>>(p_mixed, p_wT + OFF_WSEL, bsel, p_sel,
                                  nullptr, nullptr, SDIMn, DIMn);

    // 3) chunked scan; p3 writes round(sel*state)
    scan_p1<<<dim3(NCH, Bn), SDIMn>>>();
    scan_p2<<<Bn, SDIMn>>>();
    scan_p3<<<dim3(NCH, Bn), SDIMn>>>();

    // 4) remaining projections
    mma_gemm<1, 0><<<g1024, 256>>>(p_mixed, p_wT + OFF_WI, bi, p_u,
                                   nullptr, nullptr, DIMn, DIMn);
    mma_gemm<2, 0><<<g1024, 256>>>(p_mixed, p_wT + OFF_WG, bg, p_gate,
                                   nullptr, nullptr, DIMn, DIMn);

    // 5) y = (sel*st)@Wso + bso, fused gate -> z (into g_h, rounded)
    mma_gemm<0, 1><<<g1024, 256>>>(p_st, p_wT + OFF_WSO, bso, p_h,
                                   p_gate, p_u, DIMn, SDIMn);

    // 6) out = z@Wout + bout + x
    mma_gemm<0, 2><<<g1024, 256>>>(p_h, p_wT + OFF_WOUT, bout, (float*)d_out,
                                   x, nullptr, DIMn, DIMn);
}